// round 4
// baseline (speedup 1.0000x reference)
#include <cuda_runtime.h>
#include <cuda_bf16.h>
#include <math.h>

// Problem constants
// x:   [2, 1024, 1024]       fp32
// ctx: [2, 4, 1024, 1024]    fp32  -> flat [8192, 1024]
// sim: [2, 4]
// Wq:  [1024, 1024], Wkv: [1024, 2048], beta: [1], Wout: [1024,1024], bout: [1024]
// out: [2, 1024, 1024]

#define B_     2
#define N_     1024
#define DIM_   1024
#define HEADS_ 8
#define HD_    128
#define L_     4096   // m * nc = 4 * 1024
#define NC_    1024
#define M_DOCS 4

// Scratch (allocation-free rule: __device__ globals)
__device__ float g_Q[(B_*N_) * DIM_];          // 8 MB   [2048][1024] cols = h*128+d
__device__ float g_KV[(B_*L_) * (2*DIM_)];     // 64 MB  [8192][2048] k then v
__device__ float g_O[(B_*N_) * DIM_];          // 8 MB

// ---------------------------------------------------------------------------
// SGEMM: C[M,N] = A[M,K] @ B[K,N] (+ bias[N]).  M%128==0, N%128==0, K%8==0.
// 256 threads, BM=BN=128, BK=8, 8x8 microtile.
// ---------------------------------------------------------------------------
__global__ __launch_bounds__(256, 2)
void ca_sgemm128(const float* __restrict__ A, const float* __restrict__ B,
                 const float* __restrict__ bias, float* __restrict__ C,
                 int M, int N, int K)
{
    __shared__ float As[8][132];   // transposed A tile, padded
    __shared__ float Bs[8][128];

    const int tid = threadIdx.x;
    const int cRow = blockIdx.y * 128;
    const int cCol = blockIdx.x * 128;
    const int tx = tid & 15;       // 16 col-threads
    const int ty = tid >> 4;       // 16 row-threads

    float acc[8][8];
    #pragma unroll
    for (int i = 0; i < 8; i++)
        #pragma unroll
        for (int j = 0; j < 8; j++) acc[i][j] = 0.f;

    const int arow = tid >> 1;            // 0..127
    const int acol = (tid & 1) * 4;       // 0 or 4
    const int brow = tid >> 5;            // 0..7
    const int bcol = (tid & 31) * 4;      // 0..124

    const float* Aptr = A + (cRow + arow) * K + acol;
    const float* Bptr = B + brow * N + cCol + bcol;

    for (int k0 = 0; k0 < K; k0 += 8) {
        float4 a4 = *(const float4*)Aptr;  Aptr += 8;
        float4 b4 = *(const float4*)Bptr;  Bptr += 8 * N;

        As[acol + 0][arow] = a4.x;
        As[acol + 1][arow] = a4.y;
        As[acol + 2][arow] = a4.z;
        As[acol + 3][arow] = a4.w;
        *(float4*)&Bs[brow][bcol] = b4;
        __syncthreads();

        #pragma unroll
        for (int kk = 0; kk < 8; kk++) {
            float a[8], bb[8];
            *(float4*)&a[0]  = *(const float4*)&As[kk][ty * 8];
            *(float4*)&a[4]  = *(const float4*)&As[kk][ty * 8 + 4];
            *(float4*)&bb[0] = *(const float4*)&Bs[kk][tx * 8];
            *(float4*)&bb[4] = *(const float4*)&Bs[kk][tx * 8 + 4];
            #pragma unroll
            for (int i = 0; i < 8; i++)
                #pragma unroll
                for (int j = 0; j < 8; j++)
                    acc[i][j] += a[i] * bb[j];
        }
        __syncthreads();
    }

    const int crow = cRow + ty * 8;
    const int ccol = cCol + tx * 8;
    float bv[8];
    #pragma unroll
    for (int j = 0; j < 8; j++) bv[j] = bias ? bias[ccol + j] : 0.f;

    #pragma unroll
    for (int i = 0; i < 8; i++) {
        float4 c0 = make_float4(acc[i][0] + bv[0], acc[i][1] + bv[1],
                                acc[i][2] + bv[2], acc[i][3] + bv[3]);
        float4 c1 = make_float4(acc[i][4] + bv[4], acc[i][5] + bv[5],
                                acc[i][6] + bv[6], acc[i][7] + bv[7]);
        float* Cp = C + (crow + i) * N + ccol;
        *(float4*)Cp       = c0;
        *(float4*)(Cp + 4) = c1;
    }
}

// ---------------------------------------------------------------------------
// Flash attention, fp32.  One block = (b, h, 64-query tile).
// 256 threads as 16x16: thread (ty,tx) owns S rows ty*4..+3, key cols tx+16*jj,
// and O cols {tx*4..+3, 64+tx*4..+3}.
// Smem: Qs[64][132] + KVs[64][132] (K then V, serialized) + Ps[64][68].
// ---------------------------------------------------------------------------
#define ATTN_SMEM_FLOATS (64*132 + 64*132 + 64*68)

__global__ __launch_bounds__(256, 2)
void ca_attn(const float* __restrict__ Q, const float* __restrict__ KV,
             const float* __restrict__ sims, const float* __restrict__ beta_p,
             float* __restrict__ O)
{
    extern __shared__ float sm[];
    float* Qs  = sm;                 // [64][132]
    float* KVs = sm + 64 * 132;      // [64][132]
    float* Ps  = sm + 2 * 64 * 132;  // [64][68]

    const int qt = blockIdx.x;       // 0..15
    const int h  = blockIdx.y;       // 0..7
    const int b  = blockIdx.z;       // 0..1
    const int tid = threadIdx.x;
    const int tx = tid & 15;
    const int ty = tid >> 4;

    const float beta = beta_p[0];
    const int qrow0 = b * N_ + qt * 64;

    // Load Q tile (coalesced), smem writes stride-132 -> conflict-free
    for (int e = tid; e < 64 * 128; e += 256) {
        int r = e >> 7, d = e & 127;
        Qs[r * 132 + d] = Q[(qrow0 + r) * DIM_ + (h << 7) + d];
    }

    float acc[4][8];
    float mrow[4], lrow[4];
    #pragma unroll
    for (int i = 0; i < 4; i++) {
        mrow[i] = -3.0e38f; lrow[i] = 0.f;
        #pragma unroll
        for (int c = 0; c < 8; c++) acc[i][c] = 0.f;
    }
    __syncthreads();

    for (int kt = 0; kt < 64; kt++) {
        const int krow0 = b * L_ + kt * 64;
        const float simv = sims[b * M_DOCS + ((kt * 64) >> 10)] * beta;

        // ---- load K tile ----
        for (int e = tid; e < 64 * 128; e += 256) {
            int r = e >> 7, d = e & 127;
            KVs[r * 132 + d] = KV[(krow0 + r) * (2 * DIM_) + (h << 7) + d];
        }
        __syncthreads();

        // ---- S = Q @ K^T (4x4 per thread) ----
        float s[4][4];
        #pragma unroll
        for (int i = 0; i < 4; i++)
            #pragma unroll
            for (int jj = 0; jj < 4; jj++) s[i][jj] = 0.f;

        #pragma unroll 2
        for (int d = 0; d < 128; d += 4) {
            float4 q4[4], k4[4];
            #pragma unroll
            for (int i = 0; i < 4; i++)
                q4[i] = *(const float4*)&Qs[(ty * 4 + i) * 132 + d];
            #pragma unroll
            for (int jj = 0; jj < 4; jj++)
                k4[jj] = *(const float4*)&KVs[(tx + 16 * jj) * 132 + d];
            #pragma unroll
            for (int i = 0; i < 4; i++)
                #pragma unroll
                for (int jj = 0; jj < 4; jj++) {
                    s[i][jj] += q4[i].x * k4[jj].x;
                    s[i][jj] += q4[i].y * k4[jj].y;
                    s[i][jj] += q4[i].z * k4[jj].z;
                    s[i][jj] += q4[i].w * k4[jj].w;
                }
        }

        // ---- online softmax update ----
        #pragma unroll
        for (int i = 0; i < 4; i++) {
            float mt = -3.0e38f;
            #pragma unroll
            for (int jj = 0; jj < 4; jj++) {
                s[i][jj] = s[i][jj] * 0.03125f + simv;   // scale = 1024^-0.5
                mt = fmaxf(mt, s[i][jj]);
            }
            mt = fmaxf(mt, __shfl_xor_sync(0xffffffffu, mt, 1, 16));
            mt = fmaxf(mt, __shfl_xor_sync(0xffffffffu, mt, 2, 16));
            mt = fmaxf(mt, __shfl_xor_sync(0xffffffffu, mt, 4, 16));
            mt = fmaxf(mt, __shfl_xor_sync(0xffffffffu, mt, 8, 16));
            float mnew = fmaxf(mrow[i], mt);
            float corr = __expf(mrow[i] - mnew);
            mrow[i] = mnew;
            lrow[i] *= corr;
            #pragma unroll
            for (int c = 0; c < 8; c++) acc[i][c] *= corr;

            float ls = 0.f;
            #pragma unroll
            for (int jj = 0; jj < 4; jj++) {
                float p = __expf(s[i][jj] - mnew);
                Ps[(ty * 4 + i) * 68 + tx + 16 * jj] = p;
                ls += p;
            }
            ls += __shfl_xor_sync(0xffffffffu, ls, 1, 16);
            ls += __shfl_xor_sync(0xffffffffu, ls, 2, 16);
            ls += __shfl_xor_sync(0xffffffffu, ls, 4, 16);
            ls += __shfl_xor_sync(0xffffffffu, ls, 8, 16);
            lrow[i] += ls;
        }
        __syncthreads();   // all S reads of K done; Ps fully written

        // ---- load V tile into same buffer ----
        for (int e = tid; e < 64 * 128; e += 256) {
            int r = e >> 7, d = e & 127;
            KVs[r * 132 + d] = KV[(krow0 + r) * (2 * DIM_) + DIM_ + (h << 7) + d];
        }
        __syncthreads();

        // ---- O += P @ V ----
        #pragma unroll 2
        for (int j = 0; j < 64; j++) {
            float p[4];
            #pragma unroll
            for (int i = 0; i < 4; i++)
                p[i] = Ps[(ty * 4 + i) * 68 + j];
            float4 va = *(const float4*)&KVs[j * 132 + tx * 4];
            float4 vb = *(const float4*)&KVs[j * 132 + 64 + tx * 4];
            #pragma unroll
            for (int i = 0; i < 4; i++) {
                acc[i][0] += p[i] * va.x;  acc[i][1] += p[i] * va.y;
                acc[i][2] += p[i] * va.z;  acc[i][3] += p[i] * va.w;
                acc[i][4] += p[i] * vb.x;  acc[i][5] += p[i] * vb.y;
                acc[i][6] += p[i] * vb.z;  acc[i][7] += p[i] * vb.w;
            }
        }
        __syncthreads();   // protect KVs + Ps for next tile
    }

    // ---- epilogue: normalize & store [b,n,h,hd] layout ----
    #pragma unroll
    for (int i = 0; i < 4; i++) {
        float inv = 1.0f / lrow[i];
        float* op = O + (qrow0 + ty * 4 + i) * DIM_ + (h << 7);
        float4 o0 = make_float4(acc[i][0] * inv, acc[i][1] * inv,
                                acc[i][2] * inv, acc[i][3] * inv);
        float4 o1 = make_float4(acc[i][4] * inv, acc[i][5] * inv,
                                acc[i][6] * inv, acc[i][7] * inv);
        *(float4*)(op + tx * 4)      = o0;
        *(float4*)(op + 64 + tx * 4) = o1;
    }
}

// ---------------------------------------------------------------------------
extern "C" void kernel_launch(void* const* d_in, const int* in_sizes, int n_in,
                              void* d_out, int out_size)
{
    const float* x    = (const float*)d_in[0];
    const float* ctx  = (const float*)d_in[1];
    const float* sims = (const float*)d_in[2];
    const float* Wq   = (const float*)d_in[3];
    const float* Wkv  = (const float*)d_in[4];
    const float* beta = (const float*)d_in[5];
    const float* Wout = (const float*)d_in[6];
    const float* bout = (const float*)d_in[7];
    float* out = (float*)d_out;

    float *gQ, *gKV, *gO;
    cudaGetSymbolAddress((void**)&gQ,  g_Q);
    cudaGetSymbolAddress((void**)&gKV, g_KV);
    cudaGetSymbolAddress((void**)&gO,  g_O);

    const int attn_smem = ATTN_SMEM_FLOATS * (int)sizeof(float);  // ~85 KB
    cudaFuncSetAttribute(ca_attn, cudaFuncAttributeMaxDynamicSharedMemorySize,
                         attn_smem);

    // Q = x @ Wq                     [2048,1024] x [1024,1024]
    ca_sgemm128<<<dim3(DIM_ / 128, (B_ * N_) / 128), 256>>>(
        x, Wq, nullptr, gQ, B_ * N_, DIM_, DIM_);

    // KV = ctx @ Wkv                 [8192,1024] x [1024,2048]
    ca_sgemm128<<<dim3((2 * DIM_) / 128, (B_ * L_) / 128), 256>>>(
        ctx, Wkv, nullptr, gKV, B_ * L_, 2 * DIM_, DIM_);

    // attention
    ca_attn<<<dim3(N_ / 64, HEADS_, B_), 256, attn_smem>>>(
        gQ, gKV, sims, beta, gO);

    // out = O @ Wout + bout          [2048,1024] x [1024,1024]
    ca_sgemm128<<<dim3(DIM_ / 128, (B_ * N_) / 128), 256>>>(
        gO, Wout, bout, out, B_ * N_, DIM_, DIM_);
}

// round 8
// speedup vs baseline: 1.3385x; 1.3385x over previous
#include <cuda_runtime.h>
#include <cuda_bf16.h>
#include <math.h>
#include <stdint.h>

// Problem constants
#define B_     2
#define N_     1024
#define DIM_   1024
#define HEADS_ 8
#define HD_    128
#define L_     4096   // m * nc
#define M_DOCS 4

// ---------------------------------------------------------------------------
// Scratch (__device__ globals; allocation-free rule)
// ---------------------------------------------------------------------------
__device__ float g_Q [(B_*N_) * DIM_];          // 8 MB
__device__ float g_KV[(B_*L_) * (2*DIM_)];      // 64 MB
__device__ float g_O [(B_*N_) * DIM_];          // 8 MB

// split-bf16 operand buffers
__device__ __nv_bfloat16 g_xh [(B_*N_) * DIM_];
__device__ __nv_bfloat16 g_xl [(B_*N_) * DIM_];
__device__ __nv_bfloat16 g_ch [(B_*L_) * DIM_];
__device__ __nv_bfloat16 g_cl [(B_*L_) * DIM_];
__device__ __nv_bfloat16 g_oh [(B_*N_) * DIM_];
__device__ __nv_bfloat16 g_ol [(B_*N_) * DIM_];
// weights transposed to [N,K]
__device__ __nv_bfloat16 g_wqh [DIM_ * DIM_];
__device__ __nv_bfloat16 g_wql [DIM_ * DIM_];
__device__ __nv_bfloat16 g_wkvh[(2*DIM_) * DIM_];
__device__ __nv_bfloat16 g_wkvl[(2*DIM_) * DIM_];
__device__ __nv_bfloat16 g_woh [DIM_ * DIM_];
__device__ __nv_bfloat16 g_wol [DIM_ * DIM_];

// ---------------------------------------------------------------------------
// PTX helpers — ONLY non-'a' features (harness emits compute_103 PTX;
// tcgen05/.cta_group are unavailable).  cp.async + mma.sync bf16 are sm_80+.
// ---------------------------------------------------------------------------
#define CP_ASYNC16(dst, src) \
    asm volatile("cp.async.cg.shared.global [%0], [%1], 16;\n" \
                 :: "r"(dst), "l"(src) : "memory")
#define CP_ASYNC_COMMIT()  asm volatile("cp.async.commit_group;\n" ::: "memory")
#define CP_ASYNC_WAIT1()   asm volatile("cp.async.wait_group 1;\n" ::: "memory")
#define CP_ASYNC_WAIT0()   asm volatile("cp.async.wait_group 0;\n" ::: "memory")

__device__ __forceinline__ uint32_t smem_u32(const void* p) {
    uint32_t a;
    asm("{ .reg .u64 t; cvta.to.shared.u64 t, %1; cvt.u32.u64 %0, t; }"
        : "=r"(a) : "l"(p));
    return a;
}

// D += A @ B^T : m16n8k16, bf16 in, fp32 accum
__device__ __forceinline__ void mma16816(float* d, const uint32_t* a,
                                         const uint32_t* b) {
    asm volatile(
        "mma.sync.aligned.m16n8k16.row.col.f32.bf16.bf16.f32 "
        "{%0,%1,%2,%3}, {%4,%5,%6,%7}, {%8,%9}, {%0,%1,%2,%3};"
        : "+f"(d[0]), "+f"(d[1]), "+f"(d[2]), "+f"(d[3])
        : "r"(a[0]), "r"(a[1]), "r"(a[2]), "r"(a[3]), "r"(b[0]), "r"(b[1]));
}

// ---------------------------------------------------------------------------
// Conversion kernels
// ---------------------------------------------------------------------------
__global__ void conv_split(const float* __restrict__ A,
                           __nv_bfloat16* __restrict__ Ah,
                           __nv_bfloat16* __restrict__ Al, int total)
{
    int i = blockIdx.x * blockDim.x + threadIdx.x;
    if (i >= total) return;
    float v = A[i];
    __nv_bfloat16 hi = __float2bfloat16(v);
    float r = v - __bfloat162float(hi);
    Ah[i] = hi;
    Al[i] = __float2bfloat16(r);
}

// W[K,N] fp32 -> Wh/Wl [N,K] bf16 (transpose + split), 32x32 tiles
__global__ void conv_w_t(const float* __restrict__ W,
                         __nv_bfloat16* __restrict__ Wh,
                         __nv_bfloat16* __restrict__ Wl, int K, int N)
{
    __shared__ float t[32][33];
    int k0 = blockIdx.y * 32, n0 = blockIdx.x * 32;
    int tx = threadIdx.x, ty = threadIdx.y;  // 32 x 8
    #pragma unroll
    for (int i = 0; i < 32; i += 8)
        t[ty + i][tx] = W[(size_t)(k0 + ty + i) * N + n0 + tx];
    __syncthreads();
    #pragma unroll
    for (int i = 0; i < 32; i += 8) {
        float v = t[tx][ty + i];
        __nv_bfloat16 hi = __float2bfloat16(v);
        float r = v - __bfloat162float(hi);
        size_t o = (size_t)(n0 + ty + i) * K + k0 + tx;
        Wh[o] = hi;
        Wl[o] = __float2bfloat16(r);
    }
}

// ---------------------------------------------------------------------------
// mma.sync split-bf16 GEMM: C[M,N] = (Ah+Al)[M,K] @ (Bh+Bl)[N,K]^T (+ bias)
// BM=128, BN=128, BK=64, 256 threads = 8 warps (4M x 2N), warp tile 32x64.
// Double-buffered cp.async.  3 passes: Ah*Bh, Ah*Bl, Al*Bh into same accums.
// ---------------------------------------------------------------------------
#define GM_BM  128
#define GM_BN  128
#define GM_BK  64
#define GM_LDA 72                              // row stride in bf16 (144 B)
#define GM_STAGE_ELEMS ((GM_BM + GM_BN) * GM_LDA)
#define GM_SMEM_DYN (2 * GM_STAGE_ELEMS * 2)   // 73728 B

__global__ __launch_bounds__(256, 2)
void gemm_mma(const __nv_bfloat16* __restrict__ Ah,
              const __nv_bfloat16* __restrict__ Al,
              const __nv_bfloat16* __restrict__ Bh,
              const __nv_bfloat16* __restrict__ Bl,
              const float* __restrict__ bias, float* __restrict__ C,
              int M, int N, int K)
{
    extern __shared__ __align__(16) __nv_bfloat16 dsm[];

    const int tid   = threadIdx.x;
    const int wid   = tid >> 5;
    const int lane  = tid & 31;
    const int g     = lane >> 2;     // fragment group row
    const int t4    = lane & 3;      // fragment thread-in-group
    const int warpM = wid & 3;       // 0..3  -> 32-row slice
    const int warpN = wid >> 2;      // 0..1  -> 64-col slice
    const int m0 = blockIdx.y * GM_BM;
    const int n0 = blockIdx.x * GM_BN;
    const int KB = K * 2;            // bf16 row bytes
    const int kchunks = K / GM_BK;
    const int NCHUNK = 3 * kchunks;

    const uint32_t smem_base = smem_u32(dsm);

    float acc[2][8][4];
    #pragma unroll
    for (int mi = 0; mi < 2; mi++)
        #pragma unroll
        for (int ni = 0; ni < 8; ni++)
            #pragma unroll
            for (int r = 0; r < 4; r++) acc[mi][ni][r] = 0.f;

    // async loader: stage s gets chunk c.
    // A tile: 128 rows x 128 B = 1024 chunks of 16 B; B tile: same.
    // 2048 chunks total / 256 threads = 8 iterations (FIX vs R6: was 4 ->
    // half the tile was left uninitialized -> NaN).
    auto load_tile = [&](int s, int c) {
        int pass = c / kchunks;
        int kc   = c - pass * kchunks;
        const char* Asrc = (const char*)((pass < 2) ? Ah : Al)
                         + (size_t)m0 * KB + (size_t)kc * (GM_BK * 2);
        const char* Bsrc = (const char*)((pass == 1) ? Bl : Bh)
                         + (size_t)n0 * KB + (size_t)kc * (GM_BK * 2);
        uint32_t As = smem_base + s * (GM_STAGE_ELEMS * 2);
        uint32_t Bs = As + GM_BM * GM_LDA * 2;
        #pragma unroll
        for (int i = 0; i < 8; i++) {
            int u = tid + i * 256;               // 0..2047
            if (i < 4) {                         // u in [0,1024): A tile
                int row = u >> 3, ch = u & 7;
                CP_ASYNC16(As + row * (GM_LDA * 2) + ch * 16,
                           Asrc + (size_t)row * KB + ch * 16);
            } else {                             // u in [1024,2048): B tile
                int v = u - 1024;
                int row = v >> 3, ch = v & 7;
                CP_ASYNC16(Bs + row * (GM_LDA * 2) + ch * 16,
                           Bsrc + (size_t)row * KB + ch * 16);
            }
        }
        CP_ASYNC_COMMIT();
    };

    load_tile(0, 0);

    for (int c = 0; c < NCHUNK; c++) {
        if (c + 1 < NCHUNK) {
            load_tile((c + 1) & 1, c + 1);
            CP_ASYNC_WAIT1();
        } else {
            CP_ASYNC_WAIT0();
        }
        __syncthreads();

        const __nv_bfloat16* As = dsm + (c & 1) * GM_STAGE_ELEMS;
        const __nv_bfloat16* Bs = As + GM_BM * GM_LDA;

        #pragma unroll
        for (int kk = 0; kk < GM_BK; kk += 16) {
            uint32_t af[2][4], bfr[8][2];
            #pragma unroll
            for (int mi = 0; mi < 2; mi++) {
                int r0 = warpM * 32 + mi * 16 + g;
                const uint32_t* p  = (const uint32_t*)&As[r0 * GM_LDA + kk + 2 * t4];
                const uint32_t* p8 = (const uint32_t*)&As[(r0 + 8) * GM_LDA + kk + 2 * t4];
                af[mi][0] = p[0];  af[mi][2] = p[4];
                af[mi][1] = p8[0]; af[mi][3] = p8[4];
            }
            #pragma unroll
            for (int ni = 0; ni < 8; ni++) {
                int r0 = warpN * 64 + ni * 8 + g;
                const uint32_t* q = (const uint32_t*)&Bs[r0 * GM_LDA + kk + 2 * t4];
                bfr[ni][0] = q[0]; bfr[ni][1] = q[4];
            }
            #pragma unroll
            for (int mi = 0; mi < 2; mi++)
                #pragma unroll
                for (int ni = 0; ni < 8; ni++)
                    mma16816(acc[mi][ni], af[mi], bfr[ni]);
        }
        __syncthreads();
    }

    // epilogue
    #pragma unroll
    for (int mi = 0; mi < 2; mi++) {
        int row0 = m0 + warpM * 32 + mi * 16 + g;
        #pragma unroll
        for (int ni = 0; ni < 8; ni++) {
            int col = n0 + warpN * 64 + ni * 8 + 2 * t4;
            float b0 = 0.f, b1 = 0.f;
            if (bias) { b0 = bias[col]; b1 = bias[col + 1]; }
            float2 v0 = make_float2(acc[mi][ni][0] + b0, acc[mi][ni][1] + b1);
            float2 v1 = make_float2(acc[mi][ni][2] + b0, acc[mi][ni][3] + b1);
            *(float2*)(C + (size_t)row0 * N + col)       = v0;
            *(float2*)(C + (size_t)(row0 + 8) * N + col) = v1;
        }
    }
}

// ---------------------------------------------------------------------------
// Flash attention, fp32 (unchanged — next round's target)
// ---------------------------------------------------------------------------
#define ATTN_SMEM_FLOATS (64*132 + 64*132 + 64*68)

__global__ __launch_bounds__(256, 2)
void ca_attn(const float* __restrict__ Q, const float* __restrict__ KV,
             const float* __restrict__ sims, const float* __restrict__ beta_p,
             float* __restrict__ O)
{
    extern __shared__ float sm[];
    float* Qs  = sm;
    float* KVs = sm + 64 * 132;
    float* Ps  = sm + 2 * 64 * 132;

    const int qt = blockIdx.x;
    const int h  = blockIdx.y;
    const int b  = blockIdx.z;
    const int tid = threadIdx.x;
    const int tx = tid & 15;
    const int ty = tid >> 4;

    const float beta = beta_p[0];
    const int qrow0 = b * N_ + qt * 64;

    for (int e = tid; e < 64 * 128; e += 256) {
        int r = e >> 7, d = e & 127;
        Qs[r * 132 + d] = Q[(qrow0 + r) * DIM_ + (h << 7) + d];
    }

    float acc[4][8];
    float mrow[4], lrow[4];
    #pragma unroll
    for (int i = 0; i < 4; i++) {
        mrow[i] = -3.0e38f; lrow[i] = 0.f;
        #pragma unroll
        for (int c = 0; c < 8; c++) acc[i][c] = 0.f;
    }
    __syncthreads();

    for (int kt = 0; kt < 64; kt++) {
        const int krow0 = b * L_ + kt * 64;
        const float simv = sims[b * M_DOCS + ((kt * 64) >> 10)] * beta;

        for (int e = tid; e < 64 * 128; e += 256) {
            int r = e >> 7, d = e & 127;
            KVs[r * 132 + d] = KV[(krow0 + r) * (2 * DIM_) + (h << 7) + d];
        }
        __syncthreads();

        float s[4][4];
        #pragma unroll
        for (int i = 0; i < 4; i++)
            #pragma unroll
            for (int jj = 0; jj < 4; jj++) s[i][jj] = 0.f;

        #pragma unroll 2
        for (int d = 0; d < 128; d += 4) {
            float4 q4[4], k4[4];
            #pragma unroll
            for (int i = 0; i < 4; i++)
                q4[i] = *(const float4*)&Qs[(ty * 4 + i) * 132 + d];
            #pragma unroll
            for (int jj = 0; jj < 4; jj++)
                k4[jj] = *(const float4*)&KVs[(tx + 16 * jj) * 132 + d];
            #pragma unroll
            for (int i = 0; i < 4; i++)
                #pragma unroll
                for (int jj = 0; jj < 4; jj++) {
                    s[i][jj] += q4[i].x * k4[jj].x;
                    s[i][jj] += q4[i].y * k4[jj].y;
                    s[i][jj] += q4[i].z * k4[jj].z;
                    s[i][jj] += q4[i].w * k4[jj].w;
                }
        }

        #pragma unroll
        for (int i = 0; i < 4; i++) {
            float mt = -3.0e38f;
            #pragma unroll
            for (int jj = 0; jj < 4; jj++) {
                s[i][jj] = s[i][jj] * 0.03125f + simv;
                mt = fmaxf(mt, s[i][jj]);
            }
            mt = fmaxf(mt, __shfl_xor_sync(0xffffffffu, mt, 1, 16));
            mt = fmaxf(mt, __shfl_xor_sync(0xffffffffu, mt, 2, 16));
            mt = fmaxf(mt, __shfl_xor_sync(0xffffffffu, mt, 4, 16));
            mt = fmaxf(mt, __shfl_xor_sync(0xffffffffu, mt, 8, 16));
            float mnew = fmaxf(mrow[i], mt);
            float corr = __expf(mrow[i] - mnew);
            mrow[i] = mnew;
            lrow[i] *= corr;
            #pragma unroll
            for (int c = 0; c < 8; c++) acc[i][c] *= corr;

            float ls = 0.f;
            #pragma unroll
            for (int jj = 0; jj < 4; jj++) {
                float p = __expf(s[i][jj] - mnew);
                Ps[(ty * 4 + i) * 68 + tx + 16 * jj] = p;
                ls += p;
            }
            ls += __shfl_xor_sync(0xffffffffu, ls, 1, 16);
            ls += __shfl_xor_sync(0xffffffffu, ls, 2, 16);
            ls += __shfl_xor_sync(0xffffffffu, ls, 4, 16);
            ls += __shfl_xor_sync(0xffffffffu, ls, 8, 16);
            lrow[i] += ls;
        }
        __syncthreads();

        for (int e = tid; e < 64 * 128; e += 256) {
            int r = e >> 7, d = e & 127;
            KVs[r * 132 + d] = KV[(krow0 + r) * (2 * DIM_) + DIM_ + (h << 7) + d];
        }
        __syncthreads();

        #pragma unroll 2
        for (int j = 0; j < 64; j++) {
            float p[4];
            #pragma unroll
            for (int i = 0; i < 4; i++)
                p[i] = Ps[(ty * 4 + i) * 68 + j];
            float4 va = *(const float4*)&KVs[j * 132 + tx * 4];
            float4 vb = *(const float4*)&KVs[j * 132 + 64 + tx * 4];
            #pragma unroll
            for (int i = 0; i < 4; i++) {
                acc[i][0] += p[i] * va.x;  acc[i][1] += p[i] * va.y;
                acc[i][2] += p[i] * va.z;  acc[i][3] += p[i] * va.w;
                acc[i][4] += p[i] * vb.x;  acc[i][5] += p[i] * vb.y;
                acc[i][6] += p[i] * vb.z;  acc[i][7] += p[i] * vb.w;
            }
        }
        __syncthreads();
    }

    #pragma unroll
    for (int i = 0; i < 4; i++) {
        float inv = 1.0f / lrow[i];
        float* op = O + (qrow0 + ty * 4 + i) * DIM_ + (h << 7);
        float4 o0 = make_float4(acc[i][0] * inv, acc[i][1] * inv,
                                acc[i][2] * inv, acc[i][3] * inv);
        float4 o1 = make_float4(acc[i][4] * inv, acc[i][5] * inv,
                                acc[i][6] * inv, acc[i][7] * inv);
        *(float4*)(op + tx * 4)      = o0;
        *(float4*)(op + 64 + tx * 4) = o1;
    }
}

// ---------------------------------------------------------------------------
extern "C" void kernel_launch(void* const* d_in, const int* in_sizes, int n_in,
                              void* d_out, int out_size)
{
    const float* x    = (const float*)d_in[0];
    const float* ctx  = (const float*)d_in[1];
    const float* sims = (const float*)d_in[2];
    const float* Wq   = (const float*)d_in[3];
    const float* Wkv  = (const float*)d_in[4];
    const float* beta = (const float*)d_in[5];
    const float* Wout = (const float*)d_in[6];
    const float* bout = (const float*)d_in[7];
    float* out = (float*)d_out;

    float *gQ, *gKV, *gO;
    cudaGetSymbolAddress((void**)&gQ,  g_Q);
    cudaGetSymbolAddress((void**)&gKV, g_KV);
    cudaGetSymbolAddress((void**)&gO,  g_O);
    __nv_bfloat16 *xh, *xl, *ch, *cl, *oh, *ol;
    __nv_bfloat16 *wqh, *wql, *wkvh, *wkvl, *woh, *wol;
    cudaGetSymbolAddress((void**)&xh,  g_xh);
    cudaGetSymbolAddress((void**)&xl,  g_xl);
    cudaGetSymbolAddress((void**)&ch,  g_ch);
    cudaGetSymbolAddress((void**)&cl,  g_cl);
    cudaGetSymbolAddress((void**)&oh,  g_oh);
    cudaGetSymbolAddress((void**)&ol,  g_ol);
    cudaGetSymbolAddress((void**)&wqh, g_wqh);
    cudaGetSymbolAddress((void**)&wql, g_wql);
    cudaGetSymbolAddress((void**)&wkvh, g_wkvh);
    cudaGetSymbolAddress((void**)&wkvl, g_wkvl);
    cudaGetSymbolAddress((void**)&woh, g_woh);
    cudaGetSymbolAddress((void**)&wol, g_wol);

    cudaFuncSetAttribute(gemm_mma, cudaFuncAttributeMaxDynamicSharedMemorySize,
                         GM_SMEM_DYN);
    const int attn_smem = ATTN_SMEM_FLOATS * (int)sizeof(float);
    cudaFuncSetAttribute(ca_attn, cudaFuncAttributeMaxDynamicSharedMemorySize,
                         attn_smem);

    // --- input conversions ---
    {
        int t1 = B_ * N_ * DIM_;
        conv_split<<<(t1 + 255) / 256, 256>>>(x, xh, xl, t1);
        int t2 = B_ * L_ * DIM_;
        conv_split<<<(t2 + 255) / 256, 256>>>(ctx, ch, cl, t2);
        conv_w_t<<<dim3(DIM_ / 32, DIM_ / 32), dim3(32, 8)>>>(Wq, wqh, wql,
                                                              DIM_, DIM_);
        conv_w_t<<<dim3((2 * DIM_) / 32, DIM_ / 32), dim3(32, 8)>>>(
            Wkv, wkvh, wkvl, DIM_, 2 * DIM_);
        conv_w_t<<<dim3(DIM_ / 32, DIM_ / 32), dim3(32, 8)>>>(Wout, woh, wol,
                                                              DIM_, DIM_);
    }

    // Q = x @ Wq     [2048 x 1024 x 1024]
    gemm_mma<<<dim3(DIM_ / GM_BN, (B_ * N_) / GM_BM), 256, GM_SMEM_DYN>>>(
        xh, xl, wqh, wql, nullptr, gQ, B_ * N_, DIM_, DIM_);

    // KV = ctx @ Wkv [8192 x 2048 x 1024]
    gemm_mma<<<dim3((2 * DIM_) / GM_BN, (B_ * L_) / GM_BM), 256, GM_SMEM_DYN>>>(
        ch, cl, wkvh, wkvl, nullptr, gKV, B_ * L_, 2 * DIM_, DIM_);

    // attention (fp32)
    ca_attn<<<dim3(N_ / 64, HEADS_, B_), 256, attn_smem>>>(
        gQ, gKV, sims, beta, gO);

    // convert O, then out = O @ Wout + bout
    {
        int t = B_ * N_ * DIM_;
        conv_split<<<(t + 255) / 256, 256>>>(gO, oh, ol, t);
    }
    gemm_mma<<<dim3(DIM_ / GM_BN, (B_ * N_) / GM_BM), 256, GM_SMEM_DYN>>>(
        oh, ol, woh, wol, bout, out, B_ * N_, DIM_, DIM_);
}

// round 10
// speedup vs baseline: 2.9766x; 2.2238x over previous
#include <cuda_runtime.h>
#include <cuda_bf16.h>
#include <math.h>
#include <stdint.h>

// Problem constants
#define B_     2
#define N_     1024
#define DIM_   1024
#define HEADS_ 8
#define HD_    128
#define L_     4096   // m * nc
#define M_DOCS 4

// ---------------------------------------------------------------------------
// Scratch (__device__ globals; allocation-free rule)
// ---------------------------------------------------------------------------
__device__ float g_Q [(B_*N_) * DIM_];          // 8 MB
__device__ float g_KV[(B_*L_) * (2*DIM_)];      // 64 MB
__device__ float g_O [(B_*N_) * DIM_];          // 8 MB

// split-bf16 operand buffers for GEMMs
__device__ __nv_bfloat16 g_xh [(B_*N_) * DIM_];
__device__ __nv_bfloat16 g_xl [(B_*N_) * DIM_];
__device__ __nv_bfloat16 g_ch [(B_*L_) * DIM_];
__device__ __nv_bfloat16 g_cl [(B_*L_) * DIM_];
__device__ __nv_bfloat16 g_oh [(B_*N_) * DIM_];
__device__ __nv_bfloat16 g_ol [(B_*N_) * DIM_];
// weights transposed to [N,K]
__device__ __nv_bfloat16 g_wqh [DIM_ * DIM_];
__device__ __nv_bfloat16 g_wql [DIM_ * DIM_];
__device__ __nv_bfloat16 g_wkvh[(2*DIM_) * DIM_];
__device__ __nv_bfloat16 g_wkvl[(2*DIM_) * DIM_];
__device__ __nv_bfloat16 g_woh [DIM_ * DIM_];
__device__ __nv_bfloat16 g_wol [DIM_ * DIM_];

// attention operands
__device__ __nv_bfloat16 g_qb [(B_*N_) * DIM_];           // Q plain bf16
__device__ __nv_bfloat16 g_kb [(B_*L_) * DIM_];           // K plain bf16
__device__ __nv_bfloat16 g_vth[B_*HEADS_*HD_ * L_];       // V^T hi  [bh*128+d][key]
__device__ __nv_bfloat16 g_vtl[B_*HEADS_*HD_ * L_];       // V^T lo

// ---------------------------------------------------------------------------
// PTX helpers — ONLY non-'a' features (compute_103 PTX: no tcgen05).
// ---------------------------------------------------------------------------
#define CP_ASYNC16(dst, src) \
    asm volatile("cp.async.cg.shared.global [%0], [%1], 16;\n" \
                 :: "r"(dst), "l"(src) : "memory")
#define CP_ASYNC_COMMIT()  asm volatile("cp.async.commit_group;\n" ::: "memory")
#define CP_ASYNC_WAIT1()   asm volatile("cp.async.wait_group 1;\n" ::: "memory")
#define CP_ASYNC_WAIT0()   asm volatile("cp.async.wait_group 0;\n" ::: "memory")

__device__ __forceinline__ uint32_t smem_u32(const void* p) {
    uint32_t a;
    asm("{ .reg .u64 t; cvta.to.shared.u64 t, %1; cvt.u32.u64 %0, t; }"
        : "=r"(a) : "l"(p));
    return a;
}

// D += A @ B^T : m16n8k16, bf16 in, fp32 accum (layout validated in R8)
__device__ __forceinline__ void mma16816(float* d, const uint32_t* a,
                                         const uint32_t* b) {
    asm volatile(
        "mma.sync.aligned.m16n8k16.row.col.f32.bf16.bf16.f32 "
        "{%0,%1,%2,%3}, {%4,%5,%6,%7}, {%8,%9}, {%0,%1,%2,%3};"
        : "+f"(d[0]), "+f"(d[1]), "+f"(d[2]), "+f"(d[3])
        : "r"(a[0]), "r"(a[1]), "r"(a[2]), "r"(a[3]), "r"(b[0]), "r"(b[1]));
}

__device__ __forceinline__ uint32_t pack_bf16(float a, float b) {
    __nv_bfloat162 t = __float22bfloat162_rn(make_float2(a, b));
    return *(uint32_t*)&t;
}

// ---------------------------------------------------------------------------
// Conversion kernels
// ---------------------------------------------------------------------------
__global__ void conv_split(const float* __restrict__ A,
                           __nv_bfloat16* __restrict__ Ah,
                           __nv_bfloat16* __restrict__ Al, int total)
{
    int i = blockIdx.x * blockDim.x + threadIdx.x;
    if (i >= total) return;
    float v = A[i];
    __nv_bfloat16 hi = __float2bfloat16(v);
    Ah[i] = hi;
    Al[i] = __float2bfloat16(v - __bfloat162float(hi));
}

__global__ void conv_plain(const float* __restrict__ A,
                           __nv_bfloat16* __restrict__ Ab, int total)
{
    int i = blockIdx.x * blockDim.x + threadIdx.x;
    if (i >= total) return;
    Ab[i] = __float2bfloat16(A[i]);
}

// K half of g_KV -> plain bf16 [b*L][1024]
__global__ void conv_k(const float* __restrict__ KV,
                       __nv_bfloat16* __restrict__ Kb, int total)
{
    int i = blockIdx.x * blockDim.x + threadIdx.x;
    if (i >= total) return;
    int row = i >> 10, c = i & 1023;
    Kb[i] = __float2bfloat16(KV[(size_t)row * 2048 + c]);
}

// V half of g_KV -> split bf16, transposed per head: vt[(bh*128+d)][key]
__global__ void conv_vt(const float* __restrict__ KV,
                        __nv_bfloat16* __restrict__ Vh,
                        __nv_bfloat16* __restrict__ Vl)
{
    __shared__ float t[32][33];
    int key0 = blockIdx.x * 32, d0 = blockIdx.y * 32;
    int bh = blockIdx.z, b = bh >> 3, h = bh & 7;
    int tx = threadIdx.x, ty = threadIdx.y;  // 32 x 8
    #pragma unroll
    for (int i = 0; i < 32; i += 8)
        t[ty + i][tx] = KV[(size_t)(b * L_ + key0 + ty + i) * 2048
                           + 1024 + h * HD_ + d0 + tx];
    __syncthreads();
    #pragma unroll
    for (int i = 0; i < 32; i += 8) {
        float v = t[tx][ty + i];                   // key=key0+tx, d=d0+ty+i
        __nv_bfloat16 hi = __float2bfloat16(v);
        size_t o = ((size_t)bh * HD_ + d0 + ty + i) * L_ + key0 + tx;
        Vh[o] = hi;
        Vl[o] = __float2bfloat16(v - __bfloat162float(hi));
    }
}

// W[K,N] fp32 -> Wh/Wl [N,K] bf16 (transpose + split)
__global__ void conv_w_t(const float* __restrict__ W,
                         __nv_bfloat16* __restrict__ Wh,
                         __nv_bfloat16* __restrict__ Wl, int K, int N)
{
    __shared__ float t[32][33];
    int k0 = blockIdx.y * 32, n0 = blockIdx.x * 32;
    int tx = threadIdx.x, ty = threadIdx.y;
    #pragma unroll
    for (int i = 0; i < 32; i += 8)
        t[ty + i][tx] = W[(size_t)(k0 + ty + i) * N + n0 + tx];
    __syncthreads();
    #pragma unroll
    for (int i = 0; i < 32; i += 8) {
        float v = t[tx][ty + i];
        __nv_bfloat16 hi = __float2bfloat16(v);
        size_t o = (size_t)(n0 + ty + i) * K + k0 + tx;
        Wh[o] = hi;
        Wl[o] = __float2bfloat16(v - __bfloat162float(hi));
    }
}

// ---------------------------------------------------------------------------
// mma.sync split-bf16 GEMM (unchanged from R8 — passing)
// ---------------------------------------------------------------------------
#define GM_BM  128
#define GM_BN  128
#define GM_BK  64
#define GM_LDA 72
#define GM_STAGE_ELEMS ((GM_BM + GM_BN) * GM_LDA)
#define GM_SMEM_DYN (2 * GM_STAGE_ELEMS * 2)

__global__ __launch_bounds__(256, 2)
void gemm_mma(const __nv_bfloat16* __restrict__ Ah,
              const __nv_bfloat16* __restrict__ Al,
              const __nv_bfloat16* __restrict__ Bh,
              const __nv_bfloat16* __restrict__ Bl,
              const float* __restrict__ bias, float* __restrict__ C,
              int M, int N, int K)
{
    extern __shared__ __align__(16) __nv_bfloat16 dsm[];

    const int tid   = threadIdx.x;
    const int wid   = tid >> 5;
    const int lane  = tid & 31;
    const int g     = lane >> 2;
    const int t4    = lane & 3;
    const int warpM = wid & 3;
    const int warpN = wid >> 2;
    const int m0 = blockIdx.y * GM_BM;
    const int n0 = blockIdx.x * GM_BN;
    const int KB = K * 2;
    const int kchunks = K / GM_BK;
    const int NCHUNK = 3 * kchunks;

    const uint32_t smem_base = smem_u32(dsm);

    float acc[2][8][4];
    #pragma unroll
    for (int mi = 0; mi < 2; mi++)
        #pragma unroll
        for (int ni = 0; ni < 8; ni++)
            #pragma unroll
            for (int r = 0; r < 4; r++) acc[mi][ni][r] = 0.f;

    auto load_tile = [&](int s, int c) {
        int pass = c / kchunks;
        int kc   = c - pass * kchunks;
        const char* Asrc = (const char*)((pass < 2) ? Ah : Al)
                         + (size_t)m0 * KB + (size_t)kc * (GM_BK * 2);
        const char* Bsrc = (const char*)((pass == 1) ? Bl : Bh)
                         + (size_t)n0 * KB + (size_t)kc * (GM_BK * 2);
        uint32_t As = smem_base + s * (GM_STAGE_ELEMS * 2);
        uint32_t Bs = As + GM_BM * GM_LDA * 2;
        #pragma unroll
        for (int i = 0; i < 8; i++) {
            int u = tid + i * 256;
            if (i < 4) {
                int row = u >> 3, ch = u & 7;
                CP_ASYNC16(As + row * (GM_LDA * 2) + ch * 16,
                           Asrc + (size_t)row * KB + ch * 16);
            } else {
                int v = u - 1024;
                int row = v >> 3, ch = v & 7;
                CP_ASYNC16(Bs + row * (GM_LDA * 2) + ch * 16,
                           Bsrc + (size_t)row * KB + ch * 16);
            }
        }
        CP_ASYNC_COMMIT();
    };

    load_tile(0, 0);

    for (int c = 0; c < NCHUNK; c++) {
        if (c + 1 < NCHUNK) {
            load_tile((c + 1) & 1, c + 1);
            CP_ASYNC_WAIT1();
        } else {
            CP_ASYNC_WAIT0();
        }
        __syncthreads();

        const __nv_bfloat16* As = dsm + (c & 1) * GM_STAGE_ELEMS;
        const __nv_bfloat16* Bs = As + GM_BM * GM_LDA;

        #pragma unroll
        for (int kk = 0; kk < GM_BK; kk += 16) {
            uint32_t af[2][4], bfr[8][2];
            #pragma unroll
            for (int mi = 0; mi < 2; mi++) {
                int r0 = warpM * 32 + mi * 16 + g;
                const uint32_t* p  = (const uint32_t*)&As[r0 * GM_LDA + kk + 2 * t4];
                const uint32_t* p8 = (const uint32_t*)&As[(r0 + 8) * GM_LDA + kk + 2 * t4];
                af[mi][0] = p[0];  af[mi][2] = p[4];
                af[mi][1] = p8[0]; af[mi][3] = p8[4];
            }
            #pragma unroll
            for (int ni = 0; ni < 8; ni++) {
                int r0 = warpN * 64 + ni * 8 + g;
                const uint32_t* q = (const uint32_t*)&Bs[r0 * GM_LDA + kk + 2 * t4];
                bfr[ni][0] = q[0]; bfr[ni][1] = q[4];
            }
            #pragma unroll
            for (int mi = 0; mi < 2; mi++)
                #pragma unroll
                for (int ni = 0; ni < 8; ni++)
                    mma16816(acc[mi][ni], af[mi], bfr[ni]);
        }
        __syncthreads();
    }

    #pragma unroll
    for (int mi = 0; mi < 2; mi++) {
        int row0 = m0 + warpM * 32 + mi * 16 + g;
        #pragma unroll
        for (int ni = 0; ni < 8; ni++) {
            int col = n0 + warpN * 64 + ni * 8 + 2 * t4;
            float b0 = 0.f, b1 = 0.f;
            if (bias) { b0 = bias[col]; b1 = bias[col + 1]; }
            float2 v0 = make_float2(acc[mi][ni][0] + b0, acc[mi][ni][1] + b1);
            float2 v1 = make_float2(acc[mi][ni][2] + b0, acc[mi][ni][3] + b1);
            *(float2*)(C + (size_t)row0 * N + col)       = v0;
            *(float2*)(C + (size_t)(row0 + 8) * N + col) = v1;
        }
    }
}

// ---------------------------------------------------------------------------
// Flash attention on mma.sync.
// CTA = (128-query tile, head, batch); 256 threads = 8 warps, warp = 16 rows.
// QK^T plain bf16; P·V with split P (registers) x split V (precomputed):
//   O += ph*Vh + ph*Vl + pl*Vh.
// Smem: Qs[128][136] + Ks[64][136] + Vh[128][72] + Vl[128][72]  (bf16)
// ---------------------------------------------------------------------------
#define AT_LDQ 136
#define AT_LDK 136
#define AT_LDV 72
#define AT_SMEM ((128*AT_LDQ + 64*AT_LDK + 2*128*AT_LDV) * 2)   // 89088 B

__global__ __launch_bounds__(256, 1)
void ca_attn_mma(const __nv_bfloat16* __restrict__ qb,
                 const __nv_bfloat16* __restrict__ kb,
                 const __nv_bfloat16* __restrict__ vth,
                 const __nv_bfloat16* __restrict__ vtl,
                 const float* __restrict__ sims,
                 const float* __restrict__ beta_p,
                 float* __restrict__ O)
{
    extern __shared__ __align__(16) __nv_bfloat16 smattn[];
    __nv_bfloat16* Qs = smattn;
    __nv_bfloat16* Ks = Qs + 128 * AT_LDQ;
    __nv_bfloat16* Vh = Ks + 64 * AT_LDK;
    __nv_bfloat16* Vl = Vh + 128 * AT_LDV;

    const int qt = blockIdx.x, h = blockIdx.y, b = blockIdx.z;
    const int tid = threadIdx.x, wid = tid >> 5, lane = tid & 31;
    const int g = lane >> 2, t4 = lane & 3;
    const float beta = beta_p[0];
    const int qrow0 = b * N_ + qt * 128;
    const uint32_t sQ = smem_u32(Qs), sK = smem_u32(Ks);
    const uint32_t sVh = smem_u32(Vh), sVl = smem_u32(Vl);
    const size_t vbase = (size_t)(b * HEADS_ + h) * HD_ * (size_t)L_;

    // Q tile: 128 rows x 256 B
    #pragma unroll
    for (int i = 0; i < 8; i++) {
        int u = tid + i * 256, r = u >> 4, ch = u & 15;
        CP_ASYNC16(sQ + r * (AT_LDQ * 2) + ch * 16,
                   (const char*)qb + ((size_t)(qrow0 + r) * DIM_ + h * HD_) * 2 + ch * 16);
    }
    CP_ASYNC_COMMIT();

    float o[16][4];
    #pragma unroll
    for (int nj = 0; nj < 16; nj++)
        #pragma unroll
        for (int r = 0; r < 4; r++) o[nj][r] = 0.f;
    float m0r = -3.0e38f, m1r = -3.0e38f, l0r = 0.f, l1r = 0.f;

    for (int kt = 0; kt < 64; kt++) {
        // K tile: 64 rows x 256 B; V tiles: 128 rows x 128 B each
        const size_t krow0 = (size_t)(b * L_ + kt * 64);
        #pragma unroll
        for (int i = 0; i < 4; i++) {
            int u = tid + i * 256, r = u >> 4, ch = u & 15;
            CP_ASYNC16(sK + r * (AT_LDK * 2) + ch * 16,
                       (const char*)kb + ((krow0 + r) * DIM_ + h * HD_) * 2 + ch * 16);
        }
        #pragma unroll
        for (int i = 0; i < 4; i++) {
            int u = tid + i * 256, r = u >> 3, ch = u & 7;
            size_t src = (vbase + (size_t)r * L_ + kt * 64) * 2 + ch * 16;
            CP_ASYNC16(sVh + r * (AT_LDV * 2) + ch * 16, (const char*)vth + src);
        }
        #pragma unroll
        for (int i = 0; i < 4; i++) {
            int u = tid + i * 256, r = u >> 3, ch = u & 7;
            size_t src = (vbase + (size_t)r * L_ + kt * 64) * 2 + ch * 16;
            CP_ASYNC16(sVl + r * (AT_LDV * 2) + ch * 16, (const char*)vtl + src);
        }
        CP_ASYNC_COMMIT();
        CP_ASYNC_WAIT0();
        __syncthreads();

        // ---- S = Q @ K^T ----
        float s[8][4];
        #pragma unroll
        for (int nj = 0; nj < 8; nj++)
            #pragma unroll
            for (int r = 0; r < 4; r++) s[nj][r] = 0.f;

        const int qr = wid * 16;
        #pragma unroll
        for (int kk = 0; kk < 128; kk += 16) {
            uint32_t af[4];
            const uint32_t* pA  = (const uint32_t*)&Qs[(qr + g) * AT_LDQ + kk + 2 * t4];
            const uint32_t* pA8 = (const uint32_t*)&Qs[(qr + g + 8) * AT_LDQ + kk + 2 * t4];
            af[0] = pA[0]; af[1] = pA8[0]; af[2] = pA[4]; af[3] = pA8[4];
            #pragma unroll
            for (int nj = 0; nj < 8; nj++) {
                const uint32_t* pB = (const uint32_t*)&Ks[(nj * 8 + g) * AT_LDK + kk + 2 * t4];
                uint32_t bf2[2] = { pB[0], pB[4] };
                mma16816(s[nj], af, bf2);
            }
        }

        // ---- online softmax ----
        const float simv = sims[b * M_DOCS + (kt >> 4)] * beta;  // 64|1024 per doc
        float lg[8][4];
        float mt0 = -3.0e38f, mt1 = -3.0e38f;
        #pragma unroll
        for (int nj = 0; nj < 8; nj++) {
            lg[nj][0] = s[nj][0] * 0.03125f + simv;
            lg[nj][1] = s[nj][1] * 0.03125f + simv;
            lg[nj][2] = s[nj][2] * 0.03125f + simv;
            lg[nj][3] = s[nj][3] * 0.03125f + simv;
            mt0 = fmaxf(mt0, fmaxf(lg[nj][0], lg[nj][1]));
            mt1 = fmaxf(mt1, fmaxf(lg[nj][2], lg[nj][3]));
        }
        mt0 = fmaxf(mt0, __shfl_xor_sync(0xffffffffu, mt0, 1, 4));
        mt0 = fmaxf(mt0, __shfl_xor_sync(0xffffffffu, mt0, 2, 4));
        mt1 = fmaxf(mt1, __shfl_xor_sync(0xffffffffu, mt1, 1, 4));
        mt1 = fmaxf(mt1, __shfl_xor_sync(0xffffffffu, mt1, 2, 4));
        float mn0 = fmaxf(m0r, mt0), mn1 = fmaxf(m1r, mt1);
        float c0 = __expf(m0r - mn0), c1 = __expf(m1r - mn1);
        m0r = mn0; m1r = mn1; l0r *= c0; l1r *= c1;
        #pragma unroll
        for (int nj = 0; nj < 16; nj++) {
            o[nj][0] *= c0; o[nj][1] *= c0;
            o[nj][2] *= c1; o[nj][3] *= c1;
        }

        uint32_t ph01[8], ph23[8], pl01[8], pl23[8];
        #pragma unroll
        for (int nj = 0; nj < 8; nj++) {
            float p0 = __expf(lg[nj][0] - mn0), p1 = __expf(lg[nj][1] - mn0);
            float p2 = __expf(lg[nj][2] - mn1), p3 = __expf(lg[nj][3] - mn1);
            l0r += p0 + p1; l1r += p2 + p3;
            __nv_bfloat162 h01 = __float22bfloat162_rn(make_float2(p0, p1));
            __nv_bfloat162 h23 = __float22bfloat162_rn(make_float2(p2, p3));
            float2 b01 = __bfloat1622float2(h01);
            float2 b23 = __bfloat1622float2(h23);
            ph01[nj] = *(uint32_t*)&h01;
            ph23[nj] = *(uint32_t*)&h23;
            pl01[nj] = pack_bf16(p0 - b01.x, p1 - b01.y);
            pl23[nj] = pack_bf16(p2 - b23.x, p3 - b23.y);
        }

        // ---- O += ph*Vh + ph*Vl + pl*Vh ----
        #pragma unroll
        for (int kbi = 0; kbi < 4; kbi++) {
            uint32_t ah[4] = { ph01[2*kbi], ph23[2*kbi], ph01[2*kbi+1], ph23[2*kbi+1] };
            uint32_t al[4] = { pl01[2*kbi], pl23[2*kbi], pl01[2*kbi+1], pl23[2*kbi+1] };
            #pragma unroll
            for (int nj = 0; nj < 16; nj++) {
                int rowv = nj * 8 + g;
                const uint32_t* qh = (const uint32_t*)&Vh[rowv * AT_LDV + kbi * 16 + 2 * t4];
                const uint32_t* ql = (const uint32_t*)&Vl[rowv * AT_LDV + kbi * 16 + 2 * t4];
                uint32_t bh2[2] = { qh[0], qh[4] };
                uint32_t bl2[2] = { ql[0], ql[4] };
                mma16816(o[nj], ah, bh2);
                mma16816(o[nj], ah, bl2);
                mma16816(o[nj], al, bh2);
            }
        }
        __syncthreads();   // protect K/V smem before next tile's loads
    }

    // epilogue: reduce l across quad, normalize, store
    l0r += __shfl_xor_sync(0xffffffffu, l0r, 1, 4);
    l0r += __shfl_xor_sync(0xffffffffu, l0r, 2, 4);
    l1r += __shfl_xor_sync(0xffffffffu, l1r, 1, 4);
    l1r += __shfl_xor_sync(0xffffffffu, l1r, 2, 4);
    float inv0 = 1.0f / l0r, inv1 = 1.0f / l1r;

    int row0 = qrow0 + wid * 16 + g;
    float* op0 = O + (size_t)row0 * DIM_ + h * HD_;
    float* op1 = op0 + (size_t)8 * DIM_;
    #pragma unroll
    for (int nj = 0; nj < 16; nj++) {
        int col = nj * 8 + 2 * t4;
        *(float2*)(op0 + col) = make_float2(o[nj][0] * inv0, o[nj][1] * inv0);
        *(float2*)(op1 + col) = make_float2(o[nj][2] * inv1, o[nj][3] * inv1);
    }
}

// ---------------------------------------------------------------------------
extern "C" void kernel_launch(void* const* d_in, const int* in_sizes, int n_in,
                              void* d_out, int out_size)
{
    const float* x    = (const float*)d_in[0];
    const float* ctx  = (const float*)d_in[1];
    const float* sims = (const float*)d_in[2];
    const float* Wq   = (const float*)d_in[3];
    const float* Wkv  = (const float*)d_in[4];
    const float* beta = (const float*)d_in[5];
    const float* Wout = (const float*)d_in[6];
    const float* bout = (const float*)d_in[7];
    float* out = (float*)d_out;

    float *gQ, *gKV, *gO;
    cudaGetSymbolAddress((void**)&gQ,  g_Q);
    cudaGetSymbolAddress((void**)&gKV, g_KV);
    cudaGetSymbolAddress((void**)&gO,  g_O);
    __nv_bfloat16 *xh, *xl, *ch, *cl, *oh, *ol;
    __nv_bfloat16 *wqh, *wql, *wkvh, *wkvl, *woh, *wol;
    __nv_bfloat16 *qb, *kbp, *vth, *vtl;
    cudaGetSymbolAddress((void**)&xh,  g_xh);
    cudaGetSymbolAddress((void**)&xl,  g_xl);
    cudaGetSymbolAddress((void**)&ch,  g_ch);
    cudaGetSymbolAddress((void**)&cl,  g_cl);
    cudaGetSymbolAddress((void**)&oh,  g_oh);
    cudaGetSymbolAddress((void**)&ol,  g_ol);
    cudaGetSymbolAddress((void**)&wqh, g_wqh);
    cudaGetSymbolAddress((void**)&wql, g_wql);
    cudaGetSymbolAddress((void**)&wkvh, g_wkvh);
    cudaGetSymbolAddress((void**)&wkvl, g_wkvl);
    cudaGetSymbolAddress((void**)&woh, g_woh);
    cudaGetSymbolAddress((void**)&wol, g_wol);
    cudaGetSymbolAddress((void**)&qb,  g_qb);
    cudaGetSymbolAddress((void**)&kbp, g_kb);
    cudaGetSymbolAddress((void**)&vth, g_vth);
    cudaGetSymbolAddress((void**)&vtl, g_vtl);

    cudaFuncSetAttribute(gemm_mma, cudaFuncAttributeMaxDynamicSharedMemorySize,
                         GM_SMEM_DYN);
    cudaFuncSetAttribute(ca_attn_mma, cudaFuncAttributeMaxDynamicSharedMemorySize,
                         AT_SMEM);

    // --- input conversions ---
    {
        int t1 = B_ * N_ * DIM_;
        conv_split<<<(t1 + 255) / 256, 256>>>(x, xh, xl, t1);
        int t2 = B_ * L_ * DIM_;
        conv_split<<<(t2 + 255) / 256, 256>>>(ctx, ch, cl, t2);
        conv_w_t<<<dim3(DIM_ / 32, DIM_ / 32), dim3(32, 8)>>>(Wq, wqh, wql,
                                                              DIM_, DIM_);
        conv_w_t<<<dim3((2 * DIM_) / 32, DIM_ / 32), dim3(32, 8)>>>(
            Wkv, wkvh, wkvl, DIM_, 2 * DIM_);
        conv_w_t<<<dim3(DIM_ / 32, DIM_ / 32), dim3(32, 8)>>>(Wout, woh, wol,
                                                              DIM_, DIM_);
    }

    // Q = x @ Wq
    gemm_mma<<<dim3(DIM_ / GM_BN, (B_ * N_) / GM_BM), 256, GM_SMEM_DYN>>>(
        xh, xl, wqh, wql, nullptr, gQ, B_ * N_, DIM_, DIM_);

    // KV = ctx @ Wkv
    gemm_mma<<<dim3((2 * DIM_) / GM_BN, (B_ * L_) / GM_BM), 256, GM_SMEM_DYN>>>(
        ch, cl, wkvh, wkvl, nullptr, gKV, B_ * L_, 2 * DIM_, DIM_);

    // attention operand conversions
    {
        int tq = B_ * N_ * DIM_;
        conv_plain<<<(tq + 255) / 256, 256>>>(gQ, qb, tq);
        int tk = B_ * L_ * DIM_;
        conv_k<<<(tk + 255) / 256, 256>>>(gKV, kbp, tk);
        conv_vt<<<dim3(L_ / 32, HD_ / 32, B_ * HEADS_), dim3(32, 8)>>>(
            gKV, vth, vtl);
    }

    // attention (tensor-core)
    ca_attn_mma<<<dim3(N_ / 128, HEADS_, B_), 256, AT_SMEM>>>(
        qb, kbp, vth, vtl, sims, beta, gO);

    // out = O @ Wout + bout
    {
        int t = B_ * N_ * DIM_;
        conv_split<<<(t + 255) / 256, 256>>>(gO, oh, ol, t);
    }
    gemm_mma<<<dim3(DIM_ / GM_BN, (B_ * N_) / GM_BM), 256, GM_SMEM_DYN>>>(
        oh, ol, woh, wol, bout, out, B_ * N_, DIM_, DIM_);
}